// round 1
// baseline (speedup 1.0000x reference)
#include <cuda_runtime.h>
#include <cstdint>

// Problem constants (fixed shapes from reference setup_inputs)
#define BB 2
#define HH 16
#define SQ 2048
#define DD 128
#define BH (BB*HH)          // 32
#define NV (BH*SQ)          // 65536 vectors (per tensor)
#define NBLK (NV/32)        // 2048 LSH blocks
#define OUT_ELEMS (BH*SQ*DD) // 8388608

// ---------------- device scratch (static allocation: allowed) ----------------
__device__ int   g_qhash[NV];
__device__ int   g_khash[NV];
__device__ int   g_sortidx[NV];
__device__ int   g_qhs[NV];      // q_hash_sorted
__device__ float g_keep[NBLK];
__device__ float g_loss;

// ---------------- helpers ----------------
__device__ __forceinline__ unsigned long long ffma2(unsigned long long a,
                                                    unsigned long long b,
                                                    unsigned long long c) {
    unsigned long long d;
    asm("fma.rn.f32x2 %0, %1, %2, %3;" : "=l"(d) : "l"(a), "l"(b), "l"(c));
    return d;
}
__device__ __forceinline__ unsigned long long fmul2(unsigned long long a,
                                                    unsigned long long b) {
    unsigned long long d;
    asm("mul.rn.f32x2 %0, %1, %2;" : "=l"(d) : "l"(a), "l"(b));
    return d;
}
__device__ __forceinline__ unsigned long long pack2(float lo, float hi) {
    unsigned long long d;
    asm("mov.b64 %0, {%1, %2};" : "=l"(d) : "f"(lo), "f"(hi));
    return d;
}
__device__ __forceinline__ float2 unpack2(unsigned long long a) {
    float2 f;
    asm("mov.b64 {%0, %1}, %2;" : "=f"(f.x), "=f"(f.y) : "l"(a));
    return f;
}

// FMA-pipe exp (avoids MUFU bottleneck: rt_SMSP=8 -> 0.5 exp/cyc/SM).
// Accurate to ~4e-6 rel, valid for x <= 0 region we use (clamped at -87).
__device__ __forceinline__ float fexp(float x) {
    x = fmaxf(x, -87.0f);
    float t = fmaf(x, 1.4426950408889634f, 12582912.0f);   // 2^23 * 1.5 split
    int   n = __float_as_int(t) - 0x4b400000;              // round(x*log2e)
    float r = fmaf(x, 1.4426950408889634f, -(t - 12582912.0f)); // frac in [-.5,.5]
    float g = r * 0.6931471805599453f;
    float e = 1.3888888888888873e-3f;
    e = fmaf(e, g, 8.3333333333333329e-3f);
    e = fmaf(e, g, 4.1666666666666664e-2f);
    e = fmaf(e, g, 1.6666666666666666e-1f);
    e = fmaf(e, g, 0.5f);
    e = fmaf(e, g, 1.0f);
    e = fmaf(e, g, 1.0f);
    return __int_as_float(__float_as_int(e) + (n << 23));
}

// ---------------- 1) LSH hash (warp per vector) ----------------
// PERM[code] for the binary-reflected Gray permutation == code ^ (code>>1).
__global__ void hash_kernel(const float* __restrict__ q,
                            const float* __restrict__ k,
                            const float* __restrict__ proj) {
    int warp = (blockIdx.x * blockDim.x + threadIdx.x) >> 5;
    int lane = threadIdx.x & 31;
    if (warp >= 2 * NV) return;
    const float* base = (warp < NV) ? (q + (size_t)warp * DD)
                                    : (k + (size_t)(warp - NV) * DD);
    float acc[7];
#pragma unroll
    for (int r = 0; r < 7; r++) acc[r] = 0.f;
#pragma unroll
    for (int jj = 0; jj < 4; jj++) {
        int d = lane + 32 * jj;
        float x = base[d];
#pragma unroll
        for (int r = 0; r < 7; r++) acc[r] = fmaf(x, __ldg(&proj[d * 7 + r]), acc[r]);
    }
#pragma unroll
    for (int r = 0; r < 7; r++) {
#pragma unroll
        for (int off = 16; off > 0; off >>= 1)
            acc[r] += __shfl_xor_sync(0xffffffffu, acc[r], off);
    }
    if (lane == 0) {
        int code = 0;
#pragma unroll
        for (int r = 0; r < 7; r++) code |= (acc[r] > 0.f) ? (1 << r) : 0;
        int h = code ^ (code >> 1);
        if (warp < NV) g_qhash[warp] = h;
        else           g_khash[warp - NV] = h;
    }
}

// ---------------- 2) stable counting sort per (b,h) ----------------
__global__ void sort_kernel() {
    __shared__ int keys[SQ];
    __shared__ int hist[128];
    const int bh = blockIdx.x;
    const int tid = threadIdx.x;        // 128 threads
    hist[tid] = 0;
    __syncthreads();
    for (int s = tid; s < SQ; s += 128) {
        int kk = g_qhash[bh * SQ + s];
        keys[s] = kk;
        atomicAdd(&hist[kk], 1);
    }
    __syncthreads();
    int off = 0;
    for (int u = 0; u < tid; u++) off += hist[u];
    int pos = off;
    for (int s = 0; s < SQ; s++) {          // broadcast smem reads
        if (keys[s] == tid) {
            g_sortidx[bh * SQ + pos] = s;
            g_qhs[bh * SQ + pos]     = tid;
            pos++;
        }
    }
}

// ---------------- 3) block criticality ----------------
__global__ void crit_kernel() {
    int nb = blockIdx.x * blockDim.x + threadIdx.x;
    if (nb >= NBLK) return;
    int f0 = nb * 32;
    int cnt = 0;
#pragma unroll
    for (int j = 0; j < 32; j++)
        cnt += (g_khash[f0 + j] == g_qhs[f0 + j]);
    g_keep[nb] = (cnt == 0) ? 1.0f : 0.0f;
}

// ---------------- 4) dense flash attention (f32x2 FFMA) ----------------
#define BR 128
#define BC 64
#define PQ 130          // row pitch (floats): 130*4B -> LDS.64 conflict-free
#define PP 66           // P pitch: 8*66 % 32 == 16 -> 32-bank store
#define DENSE_SMEM ((BR*PQ + 2*BC*PQ + BR*PP) * 4)

__global__ void __launch_bounds__(256, 1)
dense_attn(const float* __restrict__ q, const float* __restrict__ k,
           const float* __restrict__ v, float* __restrict__ out) {
    extern __shared__ float sm[];
    float* sQ = sm;
    float* sK = sQ + BR * PQ;
    float* sV = sK + BC * PQ;
    float* sP = sV + BC * PQ;

    const int bh = blockIdx.y;
    const int q0 = blockIdx.x * BR;
    const float* qb = q + ((size_t)bh * SQ + q0) * DD;
    const float* kb = k + (size_t)bh * SQ * DD;
    const float* vb = v + (size_t)bh * SQ * DD;

    const int tid = threadIdx.x;
    const int tc  = tid & 15;     // column group (16 lanes, in-warp)
    const int tg  = tid >> 4;     // row group 0..15 (8 rows each)
    const float scale = 0.08838834764831845f;   // 1/sqrt(128), folded into Q

    for (int idx = tid; idx < BR * (DD / 4); idx += 256) {
        int r = idx >> 5, c4 = (idx & 31) << 2;
        float4 t = *(const float4*)(qb + (size_t)r * DD + c4);
        float* d = sQ + r * PQ + c4;
        d[0] = t.x * scale; d[1] = t.y * scale; d[2] = t.z * scale; d[3] = t.w * scale;
    }

    unsigned long long O[8][4];
    float m[8], l[8];
#pragma unroll
    for (int i = 0; i < 8; i++) {
        m[i] = -1e30f; l[i] = 0.f;
#pragma unroll
        for (int j = 0; j < 4; j++) O[i][j] = 0ULL;
    }

    for (int k0 = 0; k0 < SQ; k0 += BC) {
        __syncthreads();   // prev PV done (and sQ fill on first iter)
        for (int idx = tid; idx < BC * (DD / 4); idx += 256) {
            int r = idx >> 5, c4 = (idx & 31) << 2;
            float4 tk = *(const float4*)(kb + (size_t)(k0 + r) * DD + c4);
            float4 tv = *(const float4*)(vb + (size_t)(k0 + r) * DD + c4);
            float* dk = sK + r * PQ + c4;
            dk[0] = tk.x; dk[1] = tk.y; dk[2] = tk.z; dk[3] = tk.w;
            float* dv = sV + r * PQ + c4;
            dv[0] = tv.x; dv[1] = tv.y; dv[2] = tv.z; dv[3] = tv.w;
        }
        __syncthreads();

        // ---- S = Q K^T  (packed along D) ----
        unsigned long long acc[8][4];
#pragma unroll
        for (int i = 0; i < 8; i++)
#pragma unroll
            for (int j = 0; j < 4; j++) acc[i][j] = 0ULL;

#pragma unroll 4
        for (int d2 = 0; d2 < DD / 2; d2++) {
            unsigned long long qv[8], kv[4];
#pragma unroll
            for (int i = 0; i < 8; i++)
                qv[i] = *(const unsigned long long*)(sQ + (tg * 8 + i) * PQ + 2 * d2);
#pragma unroll
            for (int j = 0; j < 4; j++)
                kv[j] = *(const unsigned long long*)(sK + (tc + 16 * j) * PQ + 2 * d2);
#pragma unroll
            for (int i = 0; i < 8; i++)
#pragma unroll
                for (int j = 0; j < 4; j++)
                    acc[i][j] = ffma2(qv[i], kv[j], acc[i][j]);
        }

        // ---- online softmax ----
#pragma unroll
        for (int i = 0; i < 8; i++) {
            float s[4];
#pragma unroll
            for (int j = 0; j < 4; j++) {
                float2 p = unpack2(acc[i][j]);
                s[j] = p.x + p.y;
            }
            float mt = fmaxf(fmaxf(s[0], s[1]), fmaxf(s[2], s[3]));
#pragma unroll
            for (int off = 1; off < 16; off <<= 1)
                mt = fmaxf(mt, __shfl_xor_sync(0xffffffffu, mt, off));
            float mn = fmaxf(m[i], mt);
            float corr = fexp(m[i] - mn);
            m[i] = mn;
            float rsum = 0.f;
#pragma unroll
            for (int j = 0; j < 4; j++) {
                float p = fexp(s[j] - mn);
                sP[(tg * 8 + i) * PP + tc + 16 * j] = p;
                rsum += p;
            }
#pragma unroll
            for (int off = 1; off < 16; off <<= 1)
                rsum += __shfl_xor_sync(0xffffffffu, rsum, off);
            l[i] = l[i] * corr + rsum;
            unsigned long long c2 = pack2(corr, corr);
#pragma unroll
            for (int j = 0; j < 4; j++) O[i][j] = fmul2(O[i][j], c2);
        }
        __syncthreads();   // P visible before PV

        // ---- O += P V  (packed along D) ----
#pragma unroll 4
        for (int c = 0; c < BC; c++) {
            unsigned long long vv[4];
#pragma unroll
            for (int j = 0; j < 4; j++)
                vv[j] = *(const unsigned long long*)(sV + c * PQ + 2 * tc + 32 * j);
#pragma unroll
            for (int i = 0; i < 8; i++) {
                float pr = sP[(tg * 8 + i) * PP + c];
                unsigned long long p2 = pack2(pr, pr);
#pragma unroll
                for (int j = 0; j < 4; j++)
                    O[i][j] = ffma2(p2, vv[j], O[i][j]);
            }
        }
    }

    float* ob = out + ((size_t)bh * SQ + q0) * DD;
#pragma unroll
    for (int i = 0; i < 8; i++) {
        float inv = 1.0f / l[i];
        unsigned long long iv = pack2(inv, inv);
#pragma unroll
        for (int j = 0; j < 4; j++) {
            unsigned long long r = fmul2(O[i][j], iv);
            *(unsigned long long*)(ob + (size_t)(tg * 8 + i) * DD + 2 * (tc + 16 * j)) = r;
        }
    }
}

// ---------------- 5) loss init / finalize ----------------
__global__ void zero_loss() { g_loss = 0.f; }

__global__ void write_loss(float* out, int out_size) {
    if (out_size > OUT_ELEMS)
        out[out_size - 1] = g_loss * (1.0f / (float)OUT_ELEMS);
}

// ---------------- 6) blocked critical attention + MSE ----------------
#define PB 132
#define BLK_SMEM ((3*32*PB + 32*33) * 4)

__global__ void __launch_bounds__(128, 1)
blocked_attn(const float* __restrict__ q, const float* __restrict__ k,
             const float* __restrict__ v, const float* __restrict__ oa) {
    extern __shared__ float sm[];
    float* Qb = sm;
    float* Kb = Qb + 32 * PB;
    float* Vb = Kb + 32 * PB;
    float* Pb = Vb + 32 * PB;          // [32][33]
    __shared__ float red[4];

    const int nb = blockIdx.x;
    const int f0 = nb * 32;
    const int bh = f0 >> 11;
    const int s0 = f0 & (SQ - 1);
    const int tid = threadIdx.x;
    const float keep = g_keep[nb];
    const float scale = 0.08838834764831845f;
    const float* qp = q + (size_t)bh * SQ * DD;
    const float* kp = k + (size_t)bh * SQ * DD;
    const float* vp = v + (size_t)bh * SQ * DD;

    for (int idx = tid; idx < 32 * 32; idx += 128) {
        int r = idx >> 5, c4 = (idx & 31) << 2;
        int sq = g_sortidx[bh * SQ + s0 + r];
        float4 tq = *(const float4*)(qp + (size_t)sq * DD + c4);
        float* dq = Qb + r * PB + c4;
        dq[0] = tq.x * scale; dq[1] = tq.y * scale; dq[2] = tq.z * scale; dq[3] = tq.w * scale;
        float4 tk = *(const float4*)(kp + (size_t)(s0 + r) * DD + c4);
        float* dk = Kb + r * PB + c4;
        dk[0] = tk.x * keep; dk[1] = tk.y * keep; dk[2] = tk.z * keep; dk[3] = tk.w * keep;
        float4 tv = *(const float4*)(vp + (size_t)(s0 + r) * DD + c4);
        float* dv = Vb + r * PB + c4;
        dv[0] = tv.x; dv[1] = tv.y; dv[2] = tv.z; dv[3] = tv.w;
    }
    __syncthreads();

    const int r  = tid >> 2;   // query row 0..31
    const int cl = tid & 3;
    float sc[8];
#pragma unroll
    for (int jj = 0; jj < 8; jj++) {
        int c = cl + 4 * jj;
        float a = 0.f;
#pragma unroll 8
        for (int d = 0; d < DD; d++)
            a = fmaf(Qb[r * PB + d], Kb[c * PB + d], a);
        sc[jj] = a;
    }
    float mt = sc[0];
#pragma unroll
    for (int jj = 1; jj < 8; jj++) mt = fmaxf(mt, sc[jj]);
    mt = fmaxf(mt, __shfl_xor_sync(0xffffffffu, mt, 1));
    mt = fmaxf(mt, __shfl_xor_sync(0xffffffffu, mt, 2));
    float p[8], rsum = 0.f;
#pragma unroll
    for (int jj = 0; jj < 8; jj++) { p[jj] = fexp(sc[jj] - mt); rsum += p[jj]; }
    rsum += __shfl_xor_sync(0xffffffffu, rsum, 1);
    rsum += __shfl_xor_sync(0xffffffffu, rsum, 2);
    float linv = 1.0f / rsum;
#pragma unroll
    for (int jj = 0; jj < 8; jj++)
        Pb[r * 33 + cl + 4 * jj] = p[jj] * linv;
    __syncthreads();

    float ls = 0.f;
    const float* oar = oa + ((size_t)bh * SQ + s0 + r) * DD;
#pragma unroll 4
    for (int jj = 0; jj < 32; jj++) {
        int d = cl + 4 * jj;
        float o = 0.f;
#pragma unroll
        for (int c = 0; c < 32; c++)
            o = fmaf(Pb[r * 33 + c], Vb[c * PB + d], o);
        float diff = o - oar[d];
        ls = fmaf(diff, diff, ls);
    }
#pragma unroll
    for (int off = 16; off > 0; off >>= 1)
        ls += __shfl_xor_sync(0xffffffffu, ls, off);
    if ((tid & 31) == 0) red[tid >> 5] = ls;
    __syncthreads();
    if (tid == 0) atomicAdd(&g_loss, red[0] + red[1] + red[2] + red[3]);
}

// ---------------- launcher ----------------
extern "C" void kernel_launch(void* const* d_in, const int* in_sizes, int n_in,
                              void* d_out, int out_size) {
    (void)in_sizes; (void)n_in;
    const float* q    = (const float*)d_in[0];
    const float* k    = (const float*)d_in[1];
    const float* v    = (const float*)d_in[2];
    const float* proj = (const float*)d_in[3];
    float* out = (float*)d_out;

    cudaFuncSetAttribute(dense_attn, cudaFuncAttributeMaxDynamicSharedMemorySize, DENSE_SMEM);
    cudaFuncSetAttribute(blocked_attn, cudaFuncAttributeMaxDynamicSharedMemorySize, BLK_SMEM);

    hash_kernel<<<(2 * NV) / 8, 256>>>(q, k, proj);   // 8 warps/CTA
    sort_kernel<<<BH, 128>>>();
    crit_kernel<<<(NBLK + 255) / 256, 256>>>();
    zero_loss<<<1, 1>>>();
    dense_attn<<<dim3(SQ / BR, BH), 256, DENSE_SMEM>>>(q, k, v, out);
    blocked_attn<<<NBLK, 128, BLK_SMEM>>>(q, k, v, out);
    write_loss<<<1, 1>>>(out, out_size);
}